// round 15
// baseline (speedup 1.0000x reference)
#include <cuda_runtime.h>
#include <cuda_fp16.h>
#include <math.h>

#define N_NODES 50000
#define N_EDGES 1600000
#define BATCH   2
#define C       64
#define CAP     192
#define NBLK    ((N_NODES + 255) / 256)

// ---- scratch ----
__device__ int    g_cnt[N_NODES];
__device__ int    g_cursor[N_NODES];
__device__ float4 g_ni[N_NODES];      // {flux_b0, flux_b1, dis, 0}
__device__ __align__(16) __half g_xh[(size_t)BATCH * N_NODES * C];   // fp16 x
__device__ __align__(16) float  g_uv[(size_t)BATCH * N_NODES * 2 * C]; // [u(64)|v(64)]
// packed 8B meta: w0 = src(u16) | fb0(half)<<16 ; w1 = norm(half) | fb1(half)<<16
__device__ uint2  g_em[(size_t)N_NODES * CAP];
__device__ int    g_is64;

// ---- packed f32x2 helpers ----
__device__ __forceinline__ unsigned long long pk2(float x, float y) {
    unsigned long long r;
    asm("mov.b64 %0, {%1,%2};" : "=l"(r) : "f"(x), "f"(y));
    return r;
}
__device__ __forceinline__ void upk2(unsigned long long v, float& x, float& y) {
    asm("mov.b64 {%0,%1}, %2;" : "=f"(x), "=f"(y) : "l"(v));
}
__device__ __forceinline__ void fma2(unsigned long long& c,
                                     unsigned long long a,
                                     unsigned long long b) {
    asm("fma.rn.f32x2 %0, %1, %2, %0;" : "+l"(c) : "l"(a), "l"(b));
}
__device__ __forceinline__ void add2(unsigned long long& c, unsigned long long a) {
    asm("add.rn.f32x2 %0, %0, %1;" : "+l"(c) : "l"(a));
}
__device__ __forceinline__ float tanh_fast(float x) {
    asm("tanh.approx.f32 %0, %0;" : "+f"(x));
    return x;
}

// ---------------------------------------------------------------------------
__global__ void detect_zero_kernel(const unsigned int* __restrict__ w) {
    int i = blockIdx.x * blockDim.x + threadIdx.x;
    if (i < N_NODES) { g_cnt[i] = 0; g_cursor[i] = 0; }
    if (blockIdx.x == 0) {
        __shared__ unsigned int acc;
        if (threadIdx.x == 0) acc = 0u;
        __syncthreads();
        unsigned int v = 0u;
        for (int j = threadIdx.x; j < 4096; j += blockDim.x)
            v |= w[(size_t)2 * j * 97 + 1];
        atomicOr(&acc, v);
        __syncthreads();
        if (threadIdx.x == 0) g_is64 = (acc == 0u) ? 1 : 0;
    }
}

// x -> fp16 (independent; runs on fork stream under the CSR chain)
__global__ void xh_kernel(const float* __restrict__ x) {
    const size_t i = ((size_t)blockIdx.x * blockDim.x + threadIdx.x) * 4;
    if (i >= (size_t)BATCH * N_NODES * C) return;
    const float4 v = *(const float4*)(x + i);
    __half2 h0 = __floats2half2_rn(v.x, v.y);
    __half2 h1 = __floats2half2_rn(v.z, v.w);
    *(__half2*)(g_xh + i)     = h0;
    *(__half2*)(g_xh + i + 2) = h1;
}

// 4 edges per thread
__global__ void hist_kernel(const int* __restrict__ ei) {
    int e4 = (blockIdx.x * blockDim.x + threadIdx.x) * 4;
    if (e4 >= N_EDGES) return;
    int t0, t1, t2, t3;
    if (g_is64) {
        const int4 v0 = *(const int4*)(ei + 2 * ((size_t)N_EDGES + e4));
        const int4 v1 = *(const int4*)(ei + 2 * ((size_t)N_EDGES + e4) + 4);
        t0 = v0.x; t1 = v0.z; t2 = v1.x; t3 = v1.z;
    } else {
        const int4 v = *(const int4*)(ei + (size_t)N_EDGES + e4);
        t0 = v.x; t1 = v.y; t2 = v.z; t3 = v.w;
    }
    atomicAdd(&g_cnt[t0], 1);
    atomicAdd(&g_cnt[t1], 1);
    atomicAdd(&g_cnt[t2], 1);
    atomicAdd(&g_cnt[t3], 1);
}

__global__ void ni_kernel(const float* __restrict__ fluxes) {
    int i = blockIdx.x * blockDim.x + threadIdx.x;
    if (i < N_NODES) {
        const float dis = rsqrtf((float)(g_cnt[i] + 1));
        g_ni[i] = make_float4(fluxes[i], fluxes[N_NODES + i], dis, 0.0f);
    }
}

// ---------------------------------------------------------------------------
// fill: 2 edges/thread; packed 8B meta per edge (serves both batches).
// ---------------------------------------------------------------------------
__global__ void __launch_bounds__(256)
fill_kernel(const int* __restrict__ ei,
            const float* __restrict__ fdo) {
    int e = (blockIdx.x * blockDim.x + threadIdx.x) * 2;
    if (e >= N_EDGES) return;

    int s0, s1, t0, t1;
    if (g_is64) {
        const int4 vs = *(const int4*)(ei + 2 * (size_t)e);
        const int4 vt = *(const int4*)(ei + 2 * ((size_t)N_EDGES + e));
        s0 = vs.x; s1 = vs.z; t0 = vt.x; t1 = vt.z;
    } else {
        const int2 vs = *(const int2*)(ei + (size_t)e);
        const int2 vt = *(const int2*)(ei + (size_t)N_EDGES + e);
        s0 = vs.x; s1 = vs.y; t0 = vt.x; t1 = vt.y;
    }
    const float2 f01 = *(const float2*)(fdo + e);

#pragma unroll
    for (int k = 0; k < 2; k++) {
        const int   s  = k ? s1 : s0;
        const int   t  = k ? t1 : t0;
        const float f0 = k ? f01.y : f01.x;

        const float4 nis = __ldg(&g_ni[s]);
        const float4 nit = __ldg(&g_ni[t]);

        const float norm = nis.z * nit.z;
        const float k0 = 0.5f * (1.0f + tanh_fast(nis.x * nit.x));
        const float k1 = 0.5f * (1.0f + tanh_fast(nis.y * nit.y));
        const float fb0 = k0 * f0 + (1.0f - k0) * (1.0f - f0);
        const float fb1 = k1 * f0 + (1.0f - k1) * (1.0f - f0);

        const unsigned w0 = (unsigned)s |
            ((unsigned)__half_as_ushort(__float2half_rn(fb0)) << 16);
        const unsigned w1 = (unsigned)__half_as_ushort(__float2half_rn(norm)) |
            ((unsigned)__half_as_ushort(__float2half_rn(fb1)) << 16);

        const int pos = t * CAP + atomicAdd(&g_cursor[t], 1);
        g_em[pos] = make_uint2(w0, w1);
    }
}

// ---------------------------------------------------------------------------
// Input-space gather for ONE batch: per node accumulate
//   u[t] = x_t/deg + sum_e norm(1-fb) x_s ;  v[t] = sum_e norm*fb x_s
// One warp per node; four 8-lane groups x 4 edges/trip; one 128 B row/edge.
// ---------------------------------------------------------------------------
__global__ void __launch_bounds__(128, 6)
gather_kernel(int b) {
    __shared__ __align__(16) uint2 smeta[4][CAP];   // 6 KB / block

    const int n = (int)((blockIdx.x * blockDim.x + threadIdx.x) >> 5);
    if (n >= N_NODES) return;
    const int lane = threadIdx.x & 31;
    const int g    = lane >> 3;        // edge group 0..3
    const int l8   = lane & 7;         // 8 channels: l8*8 .. +8

    const int cnt = g_cnt[n];
    const int beg = n * CAP;
    uint2* sm = smeta[threadIdx.x >> 5];

    for (int j = lane; j < cnt; j += 32)
        sm[j] = __ldg(&g_em[beg + j]);
    __syncwarp();

    const __half* __restrict__ xb = g_xh + (size_t)b * N_NODES * C;

    unsigned long long au0 = 0ull, au1 = 0ull, au2 = 0ull, au3 = 0ull;
    unsigned long long av0 = 0ull, av1 = 0ull, av2 = 0ull, av3 = 0ull;

    if (g == 0) {   // self-loop: u += x_n / deg
        const float nrm = g_ni[n].z;   // dis
        const float n2  = nrm * nrm;   // 1/deg
        const uint4 xr = *(const uint4*)(xb + (size_t)n * C + l8 * 8);
        const float2 x0 = __half22float2(*(const __half2*)&xr.x);
        const float2 x1 = __half22float2(*(const __half2*)&xr.y);
        const float2 x2 = __half22float2(*(const __half2*)&xr.z);
        const float2 x3 = __half22float2(*(const __half2*)&xr.w);
        au0 = pk2(n2 * x0.x, n2 * x0.y);
        au1 = pk2(n2 * x1.x, n2 * x1.y);
        au2 = pk2(n2 * x2.x, n2 * x2.y);
        au3 = pk2(n2 * x3.x, n2 * x3.y);
    }

    // meta decode: w0 = src | fb0h<<16 ; w1 = normh | fb1h<<16
    auto decode = [&](int j, bool v) -> float3 {
        const uint2 t = sm[v ? j : 0];
        const float2 nf1 = __half22float2(*(const __half2*)&t.y); // (norm, fb1)
        const float2 jf0 = __half22float2(*(const __half2*)&t.x); // (junk, fb0)
        const float fb   = b ? nf1.y : jf0.y;
        const float cD   = v ? nf1.x * fb : 0.0f;
        const float cC   = v ? nf1.x - cD : 0.0f;
        return make_float3(__int_as_float((int)(t.x & 0xFFFFu)), cC, cD);
    };

    int e = g;                         // this group's slots: e, e+4, e+8, e+12
    if (e < cnt) {
        float3 m[4];
#pragma unroll
        for (int k = 0; k < 4; k++) {
            const int j = e + 4 * k;
            m[k] = decode(j, j < cnt);
        }

        for (;;) {
            // 1) issue 4 row loads (one 128 B row per edge)
            uint4 X[4];
#pragma unroll
            for (int k = 0; k < 4; k++)
                X[k] = __ldg((const uint4*)(xb +
                        (size_t)__float_as_int(m[k].x) * C + l8 * 8));

            // 2) prefetch next 4 metas from shared
            e += 16;
            const bool more = (e < cnt);
            float3 mn[4];
#pragma unroll
            for (int k = 0; k < 4; k++) {
                const int j = e + 4 * k;
                mn[k] = decode(j, j < cnt);
            }

            // 3) consume: fp16 core for u and v, flush every 2 edges
#pragma unroll
            for (int p = 0; p < 2; p++) {
                const int k0 = 2 * p, k1 = 2 * p + 1;
                const __half2 cc0 = __float2half2_rn(m[k0].y);
                const __half2 cd0 = __float2half2_rn(m[k0].z);
                const __half2 cc1 = __float2half2_rn(m[k1].y);
                const __half2 cd1 = __float2half2_rn(m[k1].z);
                const __half2* X0 = (const __half2*)&X[k0];
                const __half2* X1 = (const __half2*)&X[k1];

                __half2 hu0 = __hmul2(X0[0], cc0);
                __half2 hu1 = __hmul2(X0[1], cc0);
                __half2 hu2 = __hmul2(X0[2], cc0);
                __half2 hu3 = __hmul2(X0[3], cc0);
                __half2 hv0 = __hmul2(X0[0], cd0);
                __half2 hv1 = __hmul2(X0[1], cd0);
                __half2 hv2 = __hmul2(X0[2], cd0);
                __half2 hv3 = __hmul2(X0[3], cd0);
                hu0 = __hfma2(X1[0], cc1, hu0);
                hu1 = __hfma2(X1[1], cc1, hu1);
                hu2 = __hfma2(X1[2], cc1, hu2);
                hu3 = __hfma2(X1[3], cc1, hu3);
                hv0 = __hfma2(X1[0], cd1, hv0);
                hv1 = __hfma2(X1[1], cd1, hv1);
                hv2 = __hfma2(X1[2], cd1, hv2);
                hv3 = __hfma2(X1[3], cd1, hv3);

                float2 f;
                f = __half22float2(hu0); add2(au0, pk2(f.x, f.y));
                f = __half22float2(hu1); add2(au1, pk2(f.x, f.y));
                f = __half22float2(hu2); add2(au2, pk2(f.x, f.y));
                f = __half22float2(hu3); add2(au3, pk2(f.x, f.y));
                f = __half22float2(hv0); add2(av0, pk2(f.x, f.y));
                f = __half22float2(hv1); add2(av1, pk2(f.x, f.y));
                f = __half22float2(hv2); add2(av2, pk2(f.x, f.y));
                f = __half22float2(hv3); add2(av3, pk2(f.x, f.y));
            }

            if (!more) break;
#pragma unroll
            for (int k = 0; k < 4; k++) m[k] = mn[k];
        }
    }

    // reduce 16 floats across the 4 groups
    float u0, u1, u2, u3, u4, u5, u6, u7;
    float v0, v1, v2, v3, v4, v5, v6, v7;
    upk2(au0, u0, u1); upk2(au1, u2, u3); upk2(au2, u4, u5); upk2(au3, u6, u7);
    upk2(av0, v0, v1); upk2(av1, v2, v3); upk2(av2, v4, v5); upk2(av3, v6, v7);
#pragma unroll
    for (int d = 8; d <= 16; d <<= 1) {
        u0 += __shfl_xor_sync(0xffffffffu, u0, d);
        u1 += __shfl_xor_sync(0xffffffffu, u1, d);
        u2 += __shfl_xor_sync(0xffffffffu, u2, d);
        u3 += __shfl_xor_sync(0xffffffffu, u3, d);
        u4 += __shfl_xor_sync(0xffffffffu, u4, d);
        u5 += __shfl_xor_sync(0xffffffffu, u5, d);
        u6 += __shfl_xor_sync(0xffffffffu, u6, d);
        u7 += __shfl_xor_sync(0xffffffffu, u7, d);
        v0 += __shfl_xor_sync(0xffffffffu, v0, d);
        v1 += __shfl_xor_sync(0xffffffffu, v1, d);
        v2 += __shfl_xor_sync(0xffffffffu, v2, d);
        v3 += __shfl_xor_sync(0xffffffffu, v3, d);
        v4 += __shfl_xor_sync(0xffffffffu, v4, d);
        v5 += __shfl_xor_sync(0xffffffffu, v5, d);
        v6 += __shfl_xor_sync(0xffffffffu, v6, d);
        v7 += __shfl_xor_sync(0xffffffffu, v7, d);
    }

    if (g == 0) {
        float* row = g_uv + ((size_t)b * N_NODES + n) * (2 * C);
        *(float4*)(row + l8 * 8)         = make_float4(u0, u1, u2, u3);
        *(float4*)(row + l8 * 8 + 4)     = make_float4(u4, u5, u6, u7);
        *(float4*)(row + C + l8 * 8)     = make_float4(v0, v1, v2, v3);
        *(float4*)(row + C + l8 * 8 + 4) = make_float4(v4, v5, v6, v7);
    }
}

// ---------------------------------------------------------------------------
// Output GEMM for ONE batch: out[n,o] = Wc[o,:]·u[n] + Wd[o,:]·v[n] + bias[o]
// FFMA2 packed over adjacent K. Thread (o = tid>>2, kg = tid&3).
// ---------------------------------------------------------------------------
__global__ void __launch_bounds__(256)
gemm_out_kernel(int b,
                const float* __restrict__ Wc,
                const float* __restrict__ Wd,
                const float* __restrict__ bias,
                float* __restrict__ out) {
    const int o  = threadIdx.x >> 2;
    const int kg = threadIdx.x & 3;

    unsigned long long wu[8], wv[8];
#pragma unroll
    for (int j = 0; j < 8; j++) {
        wu[j] = pk2(Wc[o * C + kg * 16 + 2 * j], Wc[o * C + kg * 16 + 2 * j + 1]);
        wv[j] = pk2(Wd[o * C + kg * 16 + 2 * j], Wd[o * C + kg * 16 + 2 * j + 1]);
    }
    float2 bb = make_float2(0.f, 0.f);
    if ((o & 1) == 0) bb = *(const float2*)(bias + o);

    const float* __restrict__ uvb = g_uv + (size_t)b * N_NODES * (2 * C);
    float* __restrict__ outb = out + (size_t)b * N_NODES * C;

    __shared__ __align__(16) float us[4][2 * C];
    const int lr = threadIdx.x >> 6;
    const int lc = threadIdx.x & 63;

    for (int m0 = blockIdx.x * 4; m0 < N_NODES; m0 += gridDim.x * 4) {
        __syncthreads();
        us[lr][lc]     = uvb[(size_t)(m0 + lr) * (2 * C) + lc];
        us[lr][lc + C] = uvb[(size_t)(m0 + lr) * (2 * C) + lc + C];
        __syncthreads();

#pragma unroll
        for (int r = 0; r < 4; r++) {
            const float2* up = (const float2*)&us[r][kg * 16];
            const float2* vp = (const float2*)&us[r][C + kg * 16];
            unsigned long long acc = 0ull;
#pragma unroll
            for (int j = 0; j < 8; j++) fma2(acc, pk2(up[j].x, up[j].y), wu[j]);
#pragma unroll
            for (int j = 0; j < 8; j++) fma2(acc, pk2(vp[j].x, vp[j].y), wv[j]);
            float lo, hi;
            upk2(acc, lo, hi);
            float s = lo + hi;
            s += __shfl_xor_sync(0xffffffffu, s, 1);
            s += __shfl_xor_sync(0xffffffffu, s, 2);
            const float s2 = __shfl_xor_sync(0xffffffffu, s, 4);   // partner o^1
            if (kg == 0 && (o & 1) == 0)
                *(float2*)(outb + (size_t)(m0 + r) * C + o) =
                    make_float2(s + bb.x, s2 + bb.y);
        }
    }
}

// ---------------------------------------------------------------------------
extern "C" void kernel_launch(void* const* d_in, const int* in_sizes, int n_in,
                              void* d_out, int out_size) {
    const float* x    = (const float*)d_in[0];
    const int*   ei   = (const int*)d_in[1];
    const float* fdo  = (const float*)d_in[2];
    const float* flux = (const float*)d_in[3];
    const float* Wc   = (const float*)d_in[4];
    const float* Wd   = (const float*)d_in[5];
    const float* bias = (const float*)d_in[6];
    float* out = (float*)d_out;

    static cudaStream_t s2 = nullptr;
    static cudaEvent_t evA = nullptr, evXh = nullptr, evG0 = nullptr, evJ = nullptr;
    if (!s2) {
        cudaStreamCreateWithFlags(&s2, cudaStreamNonBlocking);
        cudaEventCreateWithFlags(&evA,  cudaEventDisableTiming);
        cudaEventCreateWithFlags(&evXh, cudaEventDisableTiming);
        cudaEventCreateWithFlags(&evG0, cudaEventDisableTiming);
        cudaEventCreateWithFlags(&evJ,  cudaEventDisableTiming);
    }

    // fork: x -> fp16 on s2 (overlaps CSR chain)
    cudaEventRecord(evA, 0);
    cudaStreamWaitEvent(s2, evA, 0);
    xh_kernel<<<(BATCH * N_NODES * C / 4 + 255) / 256, 256, 0, s2>>>(x);
    cudaEventRecord(evXh, s2);

    // main: CSR chain
    detect_zero_kernel<<<NBLK, 256>>>((const unsigned int*)ei);
    hist_kernel<<<(N_EDGES / 4 + 255) / 256, 256>>>(ei);
    ni_kernel<<<NBLK, 256>>>(flux);
    fill_kernel<<<(N_EDGES / 2 + 255) / 256, 256>>>(ei, fdo);

    // gather batch 0, then overlap gemm(b0) with gather batch 1
    cudaStreamWaitEvent(0, evXh, 0);
    gather_kernel<<<(N_NODES * 32 + 127) / 128, 128>>>(0);
    cudaEventRecord(evG0, 0);
    cudaStreamWaitEvent(s2, evG0, 0);
    gemm_out_kernel<<<1480, 256, 0, s2>>>(0, Wc, Wd, bias, out);
    cudaEventRecord(evJ, s2);

    gather_kernel<<<(N_NODES * 32 + 127) / 128, 128>>>(1);
    gemm_out_kernel<<<1480, 256>>>(1, Wc, Wd, bias, out);

    cudaStreamWaitEvent(0, evJ, 0);
}

// round 16
// speedup vs baseline: 1.0399x; 1.0399x over previous
#include <cuda_runtime.h>
#include <cuda_fp16.h>
#include <math.h>

#define N_NODES 50000
#define N_EDGES 1600000
#define BATCH   2
#define C       64
#define CAP     192
#define NBLK    ((N_NODES + 255) / 256)

// ---- scratch ----
__device__ int    g_cnt[N_NODES];
__device__ int    g_cursor[N_NODES];
__device__ float  g_dis[N_NODES];
__device__ float2 g_nf[N_NODES];      // {flux_b0, flux_b1}
// interleaved per (batch,node) row: [xc: 64 halfs][xd: 64 halfs] = 256 B
__device__ __align__(16) __half g_xi[(size_t)BATCH * N_NODES * 2 * C];
// packed 8B meta: w0 = src(u16) | fb0(half)<<16 ; w1 = fb1(half)
__device__ uint2  g_em[(size_t)N_NODES * CAP];
__device__ int    g_is64;

// ---- packed f32x2 helpers ----
__device__ __forceinline__ unsigned long long pk2(float x, float y) {
    unsigned long long r;
    asm("mov.b64 %0, {%1,%2};" : "=l"(r) : "f"(x), "f"(y));
    return r;
}
__device__ __forceinline__ void upk2(unsigned long long v, float& x, float& y) {
    asm("mov.b64 {%0,%1}, %2;" : "=f"(x), "=f"(y) : "l"(v));
}
__device__ __forceinline__ void fma2(unsigned long long& c,
                                     unsigned long long a,
                                     unsigned long long b) {
    asm("fma.rn.f32x2 %0, %1, %2, %0;" : "+l"(c) : "l"(a), "l"(b));
}
__device__ __forceinline__ void add2(unsigned long long& c, unsigned long long a) {
    asm("add.rn.f32x2 %0, %0, %1;" : "+l"(c) : "l"(a));
}
__device__ __forceinline__ float tanh_fast(float x) {
    asm("tanh.approx.f32 %0, %0;" : "+f"(x));
    return x;
}

// ---------------------------------------------------------------------------
// detect dtype + zero counters + build flux pairs
// ---------------------------------------------------------------------------
__global__ void detect_init_kernel(const unsigned int* __restrict__ w,
                                   const float* __restrict__ fluxes) {
    int i = blockIdx.x * blockDim.x + threadIdx.x;
    if (i < N_NODES) {
        g_cnt[i] = 0;
        g_cursor[i] = 0;
        g_nf[i] = make_float2(fluxes[i], fluxes[N_NODES + i]);
    }
    if (blockIdx.x == 0) {
        __shared__ unsigned int acc;
        if (threadIdx.x == 0) acc = 0u;
        __syncthreads();
        unsigned int v = 0u;
        for (int j = threadIdx.x; j < 4096; j += blockDim.x)
            v |= w[(size_t)2 * j * 97 + 1];
        atomicOr(&acc, v);
        __syncthreads();
        if (threadIdx.x == 0) g_is64 = (acc == 0u) ? 1 : 0;
    }
}

// 4 edges per thread
__global__ void hist_kernel(const int* __restrict__ ei) {
    int e4 = (blockIdx.x * blockDim.x + threadIdx.x) * 4;
    if (e4 >= N_EDGES) return;
    int t0, t1, t2, t3;
    if (g_is64) {
        const int4 v0 = *(const int4*)(ei + 2 * ((size_t)N_EDGES + e4));
        const int4 v1 = *(const int4*)(ei + 2 * ((size_t)N_EDGES + e4) + 4);
        t0 = v0.x; t1 = v0.z; t2 = v1.x; t3 = v1.z;
    } else {
        const int4 v = *(const int4*)(ei + (size_t)N_EDGES + e4);
        t0 = v.x; t1 = v.y; t2 = v.z; t3 = v.w;
    }
    atomicAdd(&g_cnt[t0], 1);
    atomicAdd(&g_cnt[t1], 1);
    atomicAdd(&g_cnt[t2], 1);
    atomicAdd(&g_cnt[t3], 1);
}

__global__ void dis_kernel() {
    int i = blockIdx.x * blockDim.x + threadIdx.x;
    if (i < N_NODES) g_dis[i] = rsqrtf((float)(g_cnt[i] + 1));
}

// ---------------------------------------------------------------------------
// fill: 2 edges/thread; meta {src, fb0, fb1} only — NO dependence on degrees,
// so it runs concurrently with hist/dis on another stream.
// ---------------------------------------------------------------------------
__global__ void __launch_bounds__(256)
fill_kernel(const int* __restrict__ ei,
            const float* __restrict__ fdo) {
    int e = (blockIdx.x * blockDim.x + threadIdx.x) * 2;
    if (e >= N_EDGES) return;

    int s0, s1, t0, t1;
    if (g_is64) {
        const int4 vs = *(const int4*)(ei + 2 * (size_t)e);
        const int4 vt = *(const int4*)(ei + 2 * ((size_t)N_EDGES + e));
        s0 = vs.x; s1 = vs.z; t0 = vt.x; t1 = vt.z;
    } else {
        const int2 vs = *(const int2*)(ei + (size_t)e);
        const int2 vt = *(const int2*)(ei + (size_t)N_EDGES + e);
        s0 = vs.x; s1 = vs.y; t0 = vt.x; t1 = vt.y;
    }
    const float2 f01 = *(const float2*)(fdo + e);

#pragma unroll
    for (int k = 0; k < 2; k++) {
        const int   s  = k ? s1 : s0;
        const int   t  = k ? t1 : t0;
        const float f0 = k ? f01.y : f01.x;

        const float2 nfs = __ldg(&g_nf[s]);
        const float2 nft = __ldg(&g_nf[t]);

        const float k0 = 0.5f * (1.0f + tanh_fast(nfs.x * nft.x));
        const float k1 = 0.5f * (1.0f + tanh_fast(nfs.y * nft.y));
        const float fb0 = k0 * f0 + (1.0f - k0) * (1.0f - f0);
        const float fb1 = k1 * f0 + (1.0f - k1) * (1.0f - f0);

        const unsigned w0 = (unsigned)s |
            ((unsigned)__half_as_ushort(__float2half_rn(fb0)) << 16);
        const unsigned w1 = (unsigned)__half_as_ushort(__float2half_rn(fb1));

        const int pos = t * CAP + atomicAdd(&g_cursor[t], 1);
        g_em[pos] = make_uint2(w0, w1);
    }
}

// ---------------------------------------------------------------------------
// Dual GEMM -> interleaved fp16 rows [xc(64)|xd(64)]. FFMA2-packed, kg=2 split
// (32 FFMA2 per row per thread; only 4 shuffles per row) — higher FMA-pipe
// efficiency than the old kg=4 variant. Fully independent (fork stream).
// ---------------------------------------------------------------------------
__global__ void __launch_bounds__(256)
gemm_kernel(const float* __restrict__ x,
            const float* __restrict__ Wc,
            const float* __restrict__ Wd) {
    const int kg = threadIdx.x & 1;            // k-half: 32 k each
    const int o  = (threadIdx.x >> 1) & 63;    // channel
    const int rh = threadIdx.x >> 7;           // row half (rows rh*4..+3)

    unsigned long long wp[32];
#pragma unroll
    for (int i = 0; i < 32; i++)
        wp[i] = pk2(Wc[o * C + kg * 32 + i], Wd[o * C + kg * 32 + i]);

    __shared__ __align__(16) float xs[8][C];
    const int M = BATCH * N_NODES;             // 100000, divisible by 8

    for (int m0 = blockIdx.x * 8; m0 < M; m0 += gridDim.x * 8) {
        __syncthreads();
        {
            int idx = threadIdx.x;
            xs[idx >> 6][idx & 63] = x[(size_t)(m0 + (idx >> 6)) * C + (idx & 63)];
            idx += 256;
            xs[idx >> 6][idx & 63] = x[(size_t)(m0 + (idx >> 6)) * C + (idx & 63)];
        }
        __syncthreads();

#pragma unroll
        for (int r4 = 0; r4 < 4; r4++) {
            const int row = rh * 4 + r4;
            const float4* xp = (const float4*)&xs[row][kg * 32];
            unsigned long long acc = 0ull;
#pragma unroll
            for (int j = 0; j < 8; j++) {
                float4 xv = xp[j];
                fma2(acc, pk2(xv.x, xv.x), wp[4 * j + 0]);
                fma2(acc, pk2(xv.y, xv.y), wp[4 * j + 1]);
                fma2(acc, pk2(xv.z, xv.z), wp[4 * j + 2]);
                fma2(acc, pk2(xv.w, xv.w), wp[4 * j + 3]);
            }
            float sc, sd;
            upk2(acc, sc, sd);
            sc += __shfl_xor_sync(0xffffffffu, sc, 1);   // combine kg halves
            sd += __shfl_xor_sync(0xffffffffu, sd, 1);
            const float sc2 = __shfl_xor_sync(0xffffffffu, sc, 2);  // o^1 partner
            const float sd2 = __shfl_xor_sync(0xffffffffu, sd, 2);

            if (kg == 0 && (o & 1) == 0) {
                __half* rowp = g_xi + (size_t)(m0 + row) * (2 * C);
                *(__half2*)(rowp + o)     = __floats2half2_rn(sc, sc2);
                *(__half2*)(rowp + C + o) = __floats2half2_rn(sd, sd2);
            }
        }
    }
}

// ---------------------------------------------------------------------------
// Gather (R14 structure): smem-staged 8B meta; per-edge dis_s from the
// L1-resident g_dis table; dis_t applied once in the epilogue.
// One warp per (node,batch); four 8-lane groups x 4 edges/trip.
// ---------------------------------------------------------------------------
__global__ void __launch_bounds__(128, 6)
gather_kernel(const float* __restrict__ bias, float* __restrict__ out) {
    __shared__ __align__(16) uint2 smeta[4][CAP];   // 6 KB / block

    const int w = (int)((blockIdx.x * blockDim.x + threadIdx.x) >> 5);
    if (w >= BATCH * N_NODES) return;
    const int b    = (w < N_NODES) ? 0 : 1;
    const int n    = (w < N_NODES) ? w : (w - N_NODES);
    const int lane = threadIdx.x & 31;
    const int g    = lane >> 3;        // edge group 0..3
    const int l8   = lane & 7;         // 8 channels: l8*8 .. +8

    const int cnt = g_cnt[n];
    const int beg = n * CAP;
    uint2* sm = smeta[threadIdx.x >> 5];

    for (int j = lane; j < cnt; j += 32)
        sm[j] = __ldg(&g_em[beg + j]);
    __syncwarp();

    const __half*  __restrict__ xib = g_xi + (size_t)b * N_NODES * (2 * C);

    unsigned long long a0 = 0ull, a1 = 0ull, a2 = 0ull, a3 = 0ull;

    if (g == 0) {   // self-loop: acc += dis_n * xc_n  (epilogue * dis_n => 1/deg)
        const float dn = g_dis[n];
        const uint4 xh = *(const uint4*)(xib + (size_t)n * (2 * C) + l8 * 8);
        const float2 x0 = __half22float2(*(const __half2*)&xh.x);
        const float2 x1 = __half22float2(*(const __half2*)&xh.y);
        const float2 x2 = __half22float2(*(const __half2*)&xh.z);
        const float2 x3 = __half22float2(*(const __half2*)&xh.w);
        a0 = pk2(dn * x0.x, dn * x0.y);
        a1 = pk2(dn * x1.x, dn * x1.y);
        a2 = pk2(dn * x2.x, dn * x2.y);
        a3 = pk2(dn * x3.x, dn * x3.y);
    }

    // meta decode: w0 = src | fb0h<<16 ; w1 = fb1h (low 16)
    auto decode = [&](int j, bool v) -> float3 {
        const uint2 t = sm[v ? j : 0];
        const int src = (int)(t.x & 0xFFFFu);
        const float fb = b
            ? __half2float(__ushort_as_half((unsigned short)(t.y & 0xFFFFu)))
            : __half2float(__ushort_as_half((unsigned short)(t.x >> 16)));
        const float ds = __ldg(&g_dis[src]);
        const float cD = v ? ds * fb : 0.0f;
        const float cC = v ? ds - cD : 0.0f;
        return make_float3(__int_as_float(src), cC, cD);
    };

    int e = g;                         // this group's slots: e, e+4, e+8, e+12
    if (e < cnt) {
        float3 m[4];
#pragma unroll
        for (int k = 0; k < 4; k++) {
            const int j = e + 4 * k;
            m[k] = decode(j, j < cnt);
        }

        for (;;) {
            uint4 A[4], D[4];
#pragma unroll
            for (int k = 0; k < 4; k++) {
                const __half* row = xib +
                    (size_t)__float_as_int(m[k].x) * (2 * C) + l8 * 8;
                A[k] = __ldg((const uint4*)(row));
                D[k] = __ldg((const uint4*)(row + C));
            }

            e += 16;
            const bool more = (e < cnt);
            float3 mn[4];
#pragma unroll
            for (int k = 0; k < 4; k++) {
                const int j = e + 4 * k;
                mn[k] = decode(j, j < cnt);
            }

#pragma unroll
            for (int p = 0; p < 2; p++) {
                const int k0 = 2 * p, k1 = 2 * p + 1;
                const __half2 cc0 = __float2half2_rn(m[k0].y);
                const __half2 cd0 = __float2half2_rn(m[k0].z);
                const __half2 cc1 = __float2half2_rn(m[k1].y);
                const __half2 cd1 = __float2half2_rn(m[k1].z);
                const __half2* A0 = (const __half2*)&A[k0];
                const __half2* D0 = (const __half2*)&D[k0];
                const __half2* A1 = (const __half2*)&A[k1];
                const __half2* D1 = (const __half2*)&D[k1];

                __half2 h0 = __hmul2(A0[0], cc0);
                __half2 h1 = __hmul2(A0[1], cc0);
                __half2 h2 = __hmul2(A0[2], cc0);
                __half2 h3 = __hmul2(A0[3], cc0);
                h0 = __hfma2(D0[0], cd0, h0);
                h1 = __hfma2(D0[1], cd0, h1);
                h2 = __hfma2(D0[2], cd0, h2);
                h3 = __hfma2(D0[3], cd0, h3);
                h0 = __hfma2(A1[0], cc1, h0);
                h1 = __hfma2(A1[1], cc1, h1);
                h2 = __hfma2(A1[2], cc1, h2);
                h3 = __hfma2(A1[3], cc1, h3);
                h0 = __hfma2(D1[0], cd1, h0);
                h1 = __hfma2(D1[1], cd1, h1);
                h2 = __hfma2(D1[2], cd1, h2);
                h3 = __hfma2(D1[3], cd1, h3);

                float2 f;
                f = __half22float2(h0); add2(a0, pk2(f.x, f.y));
                f = __half22float2(h1); add2(a1, pk2(f.x, f.y));
                f = __half22float2(h2); add2(a2, pk2(f.x, f.y));
                f = __half22float2(h3); add2(a3, pk2(f.x, f.y));
            }

            if (!more) break;
#pragma unroll
            for (int k = 0; k < 4; k++) m[k] = mn[k];
        }
    }

    // reduce the 4 groups
    float f0, f1, f2, f3, f4, f5, f6, f7;
    upk2(a0, f0, f1); upk2(a1, f2, f3); upk2(a2, f4, f5); upk2(a3, f6, f7);
#pragma unroll
    for (int d = 8; d <= 16; d <<= 1) {
        f0 += __shfl_xor_sync(0xffffffffu, f0, d);
        f1 += __shfl_xor_sync(0xffffffffu, f1, d);
        f2 += __shfl_xor_sync(0xffffffffu, f2, d);
        f3 += __shfl_xor_sync(0xffffffffu, f3, d);
        f4 += __shfl_xor_sync(0xffffffffu, f4, d);
        f5 += __shfl_xor_sync(0xffffffffu, f5, d);
        f6 += __shfl_xor_sync(0xffffffffu, f6, d);
        f7 += __shfl_xor_sync(0xffffffffu, f7, d);
    }

    if (g == 0) {
        const float dv = g_dis[n];     // dis_t, uniform per warp
        const float4 b0 = *(const float4*)(bias + l8 * 8);
        const float4 b1 = *(const float4*)(bias + l8 * 8 + 4);
        float* orow = out + ((size_t)b * N_NODES + n) * C + l8 * 8;
        *(float4*)(orow)     = make_float4(fmaf(dv, f0, b0.x), fmaf(dv, f1, b0.y),
                                           fmaf(dv, f2, b0.z), fmaf(dv, f3, b0.w));
        *(float4*)(orow + 4) = make_float4(fmaf(dv, f4, b1.x), fmaf(dv, f5, b1.y),
                                           fmaf(dv, f6, b1.z), fmaf(dv, f7, b1.w));
    }
}

// ---------------------------------------------------------------------------
extern "C" void kernel_launch(void* const* d_in, const int* in_sizes, int n_in,
                              void* d_out, int out_size) {
    const float* x    = (const float*)d_in[0];
    const int*   ei   = (const int*)d_in[1];
    const float* fdo  = (const float*)d_in[2];
    const float* flux = (const float*)d_in[3];
    const float* Wc   = (const float*)d_in[4];
    const float* Wd   = (const float*)d_in[5];
    const float* bias = (const float*)d_in[6];
    float* out = (float*)d_out;

    static cudaStream_t s2 = nullptr, s3 = nullptr;
    static cudaEvent_t evRoot = nullptr, evDet = nullptr,
                       evFill = nullptr, evGemm = nullptr;
    if (!s2) {
        cudaStreamCreateWithFlags(&s2, cudaStreamNonBlocking);
        cudaStreamCreateWithFlags(&s3, cudaStreamNonBlocking);
        cudaEventCreateWithFlags(&evRoot, cudaEventDisableTiming);
        cudaEventCreateWithFlags(&evDet,  cudaEventDisableTiming);
        cudaEventCreateWithFlags(&evFill, cudaEventDisableTiming);
        cudaEventCreateWithFlags(&evGemm, cudaEventDisableTiming);
    }

    // fork both helper streams from the capture origin
    cudaEventRecord(evRoot, 0);
    cudaStreamWaitEvent(s2, evRoot, 0);
    cudaStreamWaitEvent(s3, evRoot, 0);

    // s3: GEMM (fully independent)
    gemm_kernel<<<2960, 256, 0, s3>>>(x, Wc, Wd);
    cudaEventRecord(evGemm, s3);

    // main: detect -> hist -> dis
    detect_init_kernel<<<NBLK, 256>>>((const unsigned int*)ei, flux);
    cudaEventRecord(evDet, 0);

    // s2: fill (needs only detect)
    cudaStreamWaitEvent(s2, evDet, 0);
    fill_kernel<<<(N_EDGES / 2 + 255) / 256, 256, 0, s2>>>(ei, fdo);
    cudaEventRecord(evFill, s2);

    hist_kernel<<<(N_EDGES / 4 + 255) / 256, 256>>>(ei);
    dis_kernel<<<NBLK, 256>>>();

    // join all, then gather
    cudaStreamWaitEvent(0, evFill, 0);
    cudaStreamWaitEvent(0, evGemm, 0);
    gather_kernel<<<(BATCH * N_NODES * 32 + 127) / 128, 128>>>(bias, out);
}

// round 17
// speedup vs baseline: 1.2872x; 1.2379x over previous
#include <cuda_runtime.h>
#include <cuda_fp16.h>
#include <math.h>

#define N_NODES 50000
#define N_EDGES 1600000
#define BATCH   2
#define C       64
#define CAP     192
#define NBLK    ((N_NODES + 255) / 256)

// ---- scratch ----
__device__ int    g_cnt[N_NODES];
__device__ int    g_cursor[N_NODES];
__device__ float  g_dis[N_NODES];
__device__ float2 g_nf[N_NODES];      // {flux_b0, flux_b1}
// interleaved per (batch,node) row: [xc: 64 halfs][xd: 64 halfs] = 256 B
__device__ __align__(16) __half g_xi[(size_t)BATCH * N_NODES * 2 * C];
// packed 8B meta: w0 = src(u16) | fb0(half)<<16 ; w1 = fb1(half) (hi16 spare)
__device__ uint2  g_em[(size_t)N_NODES * CAP];
__device__ int    g_is64;

// ---- packed f32x2 helpers ----
__device__ __forceinline__ unsigned long long pk2(float x, float y) {
    unsigned long long r;
    asm("mov.b64 %0, {%1,%2};" : "=l"(r) : "f"(x), "f"(y));
    return r;
}
__device__ __forceinline__ void upk2(unsigned long long v, float& x, float& y) {
    asm("mov.b64 {%0,%1}, %2;" : "=f"(x), "=f"(y) : "l"(v));
}
__device__ __forceinline__ void fma2(unsigned long long& c,
                                     unsigned long long a,
                                     unsigned long long b) {
    asm("fma.rn.f32x2 %0, %1, %2, %0;" : "+l"(c) : "l"(a), "l"(b));
}
__device__ __forceinline__ void add2(unsigned long long& c, unsigned long long a) {
    asm("add.rn.f32x2 %0, %0, %1;" : "+l"(c) : "l"(a));
}
__device__ __forceinline__ float tanh_fast(float x) {
    asm("tanh.approx.f32 %0, %0;" : "+f"(x));
    return x;
}

// ---------------------------------------------------------------------------
// detect dtype + zero counters + build flux pairs
// ---------------------------------------------------------------------------
__global__ void detect_init_kernel(const unsigned int* __restrict__ w,
                                   const float* __restrict__ fluxes) {
    int i = blockIdx.x * blockDim.x + threadIdx.x;
    if (i < N_NODES) {
        g_cnt[i] = 0;
        g_cursor[i] = 0;
        g_nf[i] = make_float2(fluxes[i], fluxes[N_NODES + i]);
    }
    if (blockIdx.x == 0) {
        __shared__ unsigned int acc;
        if (threadIdx.x == 0) acc = 0u;
        __syncthreads();
        unsigned int v = 0u;
        for (int j = threadIdx.x; j < 4096; j += blockDim.x)
            v |= w[(size_t)2 * j * 97 + 1];
        atomicOr(&acc, v);
        __syncthreads();
        if (threadIdx.x == 0) g_is64 = (acc == 0u) ? 1 : 0;
    }
}

// 4 edges per thread
__global__ void hist_kernel(const int* __restrict__ ei) {
    int e4 = (blockIdx.x * blockDim.x + threadIdx.x) * 4;
    if (e4 >= N_EDGES) return;
    int t0, t1, t2, t3;
    if (g_is64) {
        const int4 v0 = *(const int4*)(ei + 2 * ((size_t)N_EDGES + e4));
        const int4 v1 = *(const int4*)(ei + 2 * ((size_t)N_EDGES + e4) + 4);
        t0 = v0.x; t1 = v0.z; t2 = v1.x; t3 = v1.z;
    } else {
        const int4 v = *(const int4*)(ei + (size_t)N_EDGES + e4);
        t0 = v.x; t1 = v.y; t2 = v.z; t3 = v.w;
    }
    atomicAdd(&g_cnt[t0], 1);
    atomicAdd(&g_cnt[t1], 1);
    atomicAdd(&g_cnt[t2], 1);
    atomicAdd(&g_cnt[t3], 1);
}

__global__ void dis_kernel() {
    int i = blockIdx.x * blockDim.x + threadIdx.x;
    if (i < N_NODES) g_dis[i] = rsqrtf((float)(g_cnt[i] + 1));
}

// ---------------------------------------------------------------------------
// fill: 2 edges/thread; meta {src, fb0, fb1} — no dis dependence, runs on s2
// concurrently with hist/dis.
// ---------------------------------------------------------------------------
__global__ void __launch_bounds__(256)
fill_kernel(const int* __restrict__ ei,
            const float* __restrict__ fdo) {
    int e = (blockIdx.x * blockDim.x + threadIdx.x) * 2;
    if (e >= N_EDGES) return;

    int s0, s1, t0, t1;
    if (g_is64) {
        const int4 vs = *(const int4*)(ei + 2 * (size_t)e);
        const int4 vt = *(const int4*)(ei + 2 * ((size_t)N_EDGES + e));
        s0 = vs.x; s1 = vs.z; t0 = vt.x; t1 = vt.z;
    } else {
        const int2 vs = *(const int2*)(ei + (size_t)e);
        const int2 vt = *(const int2*)(ei + (size_t)N_EDGES + e);
        s0 = vs.x; s1 = vs.y; t0 = vt.x; t1 = vt.y;
    }
    const float2 f01 = *(const float2*)(fdo + e);

#pragma unroll
    for (int k = 0; k < 2; k++) {
        const int   s  = k ? s1 : s0;
        const int   t  = k ? t1 : t0;
        const float f0 = k ? f01.y : f01.x;

        const float2 nfs = __ldg(&g_nf[s]);
        const float2 nft = __ldg(&g_nf[t]);

        const float k0 = 0.5f * (1.0f + tanh_fast(nfs.x * nft.x));
        const float k1 = 0.5f * (1.0f + tanh_fast(nfs.y * nft.y));
        const float fb0 = k0 * f0 + (1.0f - k0) * (1.0f - f0);
        const float fb1 = k1 * f0 + (1.0f - k1) * (1.0f - f0);

        const unsigned w0 = (unsigned)s |
            ((unsigned)__half_as_ushort(__float2half_rn(fb0)) << 16);
        const unsigned w1 = (unsigned)__half_as_ushort(__float2half_rn(fb1));

        const int pos = t * CAP + atomicAdd(&g_cursor[t], 1);
        g_em[pos] = make_uint2(w0, w1);
    }
}

// ---------------------------------------------------------------------------
// Dual GEMM for ONE batch -> interleaved fp16 rows [xc(64)|xd(64)].
// R14's verified kg=4 FFMA2 kernel, restricted to rows of batch b.
// ---------------------------------------------------------------------------
__global__ void __launch_bounds__(256)
gemm_kernel(int b,
            const float* __restrict__ x,
            const float* __restrict__ Wc,
            const float* __restrict__ Wd) {
    const int o  = threadIdx.x >> 2;
    const int kg = threadIdx.x & 3;

    unsigned long long wp[16];
#pragma unroll
    for (int i = 0; i < 16; i++)
        wp[i] = pk2(Wc[o * C + kg * 16 + i], Wd[o * C + kg * 16 + i]);

    const float* __restrict__ xb = x + (size_t)b * N_NODES * C;
    __half* __restrict__ xib = g_xi + (size_t)b * N_NODES * (2 * C);

    __shared__ __align__(16) float xs[4][C];
    const int lr = threadIdx.x >> 6;
    const int lc = threadIdx.x & 63;

    for (int m0 = blockIdx.x * 4; m0 < N_NODES; m0 += gridDim.x * 4) {
        __syncthreads();
        xs[lr][lc] = xb[(size_t)(m0 + lr) * C + lc];
        __syncthreads();

#pragma unroll
        for (int r2 = 0; r2 < 4; r2++) {
            const float4* xp = (const float4*)&xs[r2][kg * 16];
            unsigned long long acc = 0ull;
#pragma unroll
            for (int j = 0; j < 4; j++) {
                float4 xv = xp[j];
                fma2(acc, pk2(xv.x, xv.x), wp[4 * j + 0]);
                fma2(acc, pk2(xv.y, xv.y), wp[4 * j + 1]);
                fma2(acc, pk2(xv.z, xv.z), wp[4 * j + 2]);
                fma2(acc, pk2(xv.w, xv.w), wp[4 * j + 3]);
            }
            float sc, sd;
            upk2(acc, sc, sd);
            sc += __shfl_xor_sync(0xffffffffu, sc, 1);
            sc += __shfl_xor_sync(0xffffffffu, sc, 2);
            sd += __shfl_xor_sync(0xffffffffu, sd, 1);
            sd += __shfl_xor_sync(0xffffffffu, sd, 2);
            float sc2 = __shfl_xor_sync(0xffffffffu, sc, 4);
            float sd2 = __shfl_xor_sync(0xffffffffu, sd, 4);

            if (kg == 0 && (o & 1) == 0) {
                __half* row = xib + (size_t)(m0 + r2) * (2 * C);
                *(__half2*)(row + o)     = __floats2half2_rn(sc, sc2);
                *(__half2*)(row + C + o) = __floats2half2_rn(sd, sd2);
            }
        }
    }
}

// ---------------------------------------------------------------------------
// Gather for ONE batch: stage meta in smem, then a one-time warp pre-pass ORs
// dis[src] (fp16) into the spare hi-16 of w1 — hot loop stays smem-only.
// Epilogue: out = bias + dis_t * acc. Self-loop: acc += dis_n * xc_n.
// ---------------------------------------------------------------------------
__global__ void __launch_bounds__(128, 6)
gather_kernel(int b, const float* __restrict__ bias, float* __restrict__ out) {
    __shared__ __align__(16) uint2 smeta[4][CAP];   // 6 KB / block

    const int n = (int)((blockIdx.x * blockDim.x + threadIdx.x) >> 5);
    if (n >= N_NODES) return;
    const int lane = threadIdx.x & 31;
    const int g    = lane >> 3;        // edge group 0..3
    const int l8   = lane & 7;         // 8 channels: l8*8 .. +8

    const int cnt = g_cnt[n];
    const int beg = n * CAP;
    uint2* sm = smeta[threadIdx.x >> 5];

    // stage bucket + pre-pass: bake dis[src] (fp16) into w1 hi bits
    for (int j = lane; j < cnt; j += 32) {
        uint2 t = __ldg(&g_em[beg + j]);
        const float ds = __ldg(&g_dis[t.x & 0xFFFFu]);
        t.y |= ((unsigned)__half_as_ushort(__float2half_rn(ds)) << 16);
        sm[j] = t;
    }
    __syncwarp();

    const __half* __restrict__ xib = g_xi + (size_t)b * N_NODES * (2 * C);

    unsigned long long a0 = 0ull, a1 = 0ull, a2 = 0ull, a3 = 0ull;

    if (g == 0) {   // self-loop: acc += dis_n * xc_n (epilogue dis_n => 1/deg)
        const float dn = g_dis[n];
        const uint4 xh = *(const uint4*)(xib + (size_t)n * (2 * C) + l8 * 8);
        const float2 x0 = __half22float2(*(const __half2*)&xh.x);
        const float2 x1 = __half22float2(*(const __half2*)&xh.y);
        const float2 x2 = __half22float2(*(const __half2*)&xh.z);
        const float2 x3 = __half22float2(*(const __half2*)&xh.w);
        a0 = pk2(dn * x0.x, dn * x0.y);
        a1 = pk2(dn * x1.x, dn * x1.y);
        a2 = pk2(dn * x2.x, dn * x2.y);
        a3 = pk2(dn * x3.x, dn * x3.y);
    }

    // decode (pure LDS): w0 = src | fb0h<<16 ; w1 = fb1h | dsh<<16
    auto decode = [&](int j, bool v) -> float3 {
        const uint2 t = sm[v ? j : 0];
        const float2 f1d = __half22float2(*(const __half2*)&t.y); // (fb1, ds)
        const float fb = b ? f1d.x
            : __half2float(__ushort_as_half((unsigned short)(t.x >> 16)));
        const float cD = v ? f1d.y * fb : 0.0f;
        const float cC = v ? f1d.y - cD : 0.0f;
        return make_float3(__int_as_float((int)(t.x & 0xFFFFu)), cC, cD);
    };

    int e = g;                         // this group's slots: e, e+4, e+8, e+12
    if (e < cnt) {
        float3 m[4];
#pragma unroll
        for (int k = 0; k < 4; k++) {
            const int j = e + 4 * k;
            m[k] = decode(j, j < cnt);
        }

        for (;;) {
            uint4 A[4], D[4];
#pragma unroll
            for (int k = 0; k < 4; k++) {
                const __half* row = xib +
                    (size_t)__float_as_int(m[k].x) * (2 * C) + l8 * 8;
                A[k] = __ldg((const uint4*)(row));
                D[k] = __ldg((const uint4*)(row + C));
            }

            e += 16;
            const bool more = (e < cnt);
            float3 mn[4];
#pragma unroll
            for (int k = 0; k < 4; k++) {
                const int j = e + 4 * k;
                mn[k] = decode(j, j < cnt);
            }

#pragma unroll
            for (int p = 0; p < 2; p++) {
                const int k0 = 2 * p, k1 = 2 * p + 1;
                const __half2 cc0 = __float2half2_rn(m[k0].y);
                const __half2 cd0 = __float2half2_rn(m[k0].z);
                const __half2 cc1 = __float2half2_rn(m[k1].y);
                const __half2 cd1 = __float2half2_rn(m[k1].z);
                const __half2* A0 = (const __half2*)&A[k0];
                const __half2* D0 = (const __half2*)&D[k0];
                const __half2* A1 = (const __half2*)&A[k1];
                const __half2* D1 = (const __half2*)&D[k1];

                __half2 h0 = __hmul2(A0[0], cc0);
                __half2 h1 = __hmul2(A0[1], cc0);
                __half2 h2 = __hmul2(A0[2], cc0);
                __half2 h3 = __hmul2(A0[3], cc0);
                h0 = __hfma2(D0[0], cd0, h0);
                h1 = __hfma2(D0[1], cd0, h1);
                h2 = __hfma2(D0[2], cd0, h2);
                h3 = __hfma2(D0[3], cd0, h3);
                h0 = __hfma2(A1[0], cc1, h0);
                h1 = __hfma2(A1[1], cc1, h1);
                h2 = __hfma2(A1[2], cc1, h2);
                h3 = __hfma2(A1[3], cc1, h3);
                h0 = __hfma2(D1[0], cd1, h0);
                h1 = __hfma2(D1[1], cd1, h1);
                h2 = __hfma2(D1[2], cd1, h2);
                h3 = __hfma2(D1[3], cd1, h3);

                float2 f;
                f = __half22float2(h0); add2(a0, pk2(f.x, f.y));
                f = __half22float2(h1); add2(a1, pk2(f.x, f.y));
                f = __half22float2(h2); add2(a2, pk2(f.x, f.y));
                f = __half22float2(h3); add2(a3, pk2(f.x, f.y));
            }

            if (!more) break;
#pragma unroll
            for (int k = 0; k < 4; k++) m[k] = mn[k];
        }
    }

    // reduce the 4 groups
    float f0, f1, f2, f3, f4, f5, f6, f7;
    upk2(a0, f0, f1); upk2(a1, f2, f3); upk2(a2, f4, f5); upk2(a3, f6, f7);
#pragma unroll
    for (int d = 8; d <= 16; d <<= 1) {
        f0 += __shfl_xor_sync(0xffffffffu, f0, d);
        f1 += __shfl_xor_sync(0xffffffffu, f1, d);
        f2 += __shfl_xor_sync(0xffffffffu, f2, d);
        f3 += __shfl_xor_sync(0xffffffffu, f3, d);
        f4 += __shfl_xor_sync(0xffffffffu, f4, d);
        f5 += __shfl_xor_sync(0xffffffffu, f5, d);
        f6 += __shfl_xor_sync(0xffffffffu, f6, d);
        f7 += __shfl_xor_sync(0xffffffffu, f7, d);
    }

    if (g == 0) {
        const float dv = g_dis[n];     // dis_t, uniform per warp
        const float4 b0 = *(const float4*)(bias + l8 * 8);
        const float4 b1 = *(const float4*)(bias + l8 * 8 + 4);
        float* orow = out + ((size_t)b * N_NODES + n) * C + l8 * 8;
        *(float4*)(orow)     = make_float4(fmaf(dv, f0, b0.x), fmaf(dv, f1, b0.y),
                                           fmaf(dv, f2, b0.z), fmaf(dv, f3, b0.w));
        *(float4*)(orow + 4) = make_float4(fmaf(dv, f4, b1.x), fmaf(dv, f5, b1.y),
                                           fmaf(dv, f6, b1.z), fmaf(dv, f7, b1.w));
    }
}

// ---------------------------------------------------------------------------
extern "C" void kernel_launch(void* const* d_in, const int* in_sizes, int n_in,
                              void* d_out, int out_size) {
    const float* x    = (const float*)d_in[0];
    const int*   ei   = (const int*)d_in[1];
    const float* fdo  = (const float*)d_in[2];
    const float* flux = (const float*)d_in[3];
    const float* Wc   = (const float*)d_in[4];
    const float* Wd   = (const float*)d_in[5];
    const float* bias = (const float*)d_in[6];
    float* out = (float*)d_out;

    static cudaStream_t s2 = nullptr, s3 = nullptr;
    static cudaEvent_t evRoot = nullptr, evDet = nullptr, evFill = nullptr,
                       evG0 = nullptr, evG1 = nullptr;
    if (!s2) {
        cudaStreamCreateWithFlags(&s2, cudaStreamNonBlocking);
        cudaStreamCreateWithFlags(&s3, cudaStreamNonBlocking);
        cudaEventCreateWithFlags(&evRoot, cudaEventDisableTiming);
        cudaEventCreateWithFlags(&evDet,  cudaEventDisableTiming);
        cudaEventCreateWithFlags(&evFill, cudaEventDisableTiming);
        cudaEventCreateWithFlags(&evG0,   cudaEventDisableTiming);
        cudaEventCreateWithFlags(&evG1,   cudaEventDisableTiming);
    }

    cudaEventRecord(evRoot, 0);
    cudaStreamWaitEvent(s3, evRoot, 0);

    // s3: per-batch GEMMs (independent of edge chain)
    gemm_kernel<<<1480, 256, 0, s3>>>(0, x, Wc, Wd);
    cudaEventRecord(evG0, s3);
    gemm_kernel<<<1480, 256, 0, s3>>>(1, x, Wc, Wd);
    cudaEventRecord(evG1, s3);

    // main: detect -> (fork fill) -> hist -> dis
    detect_init_kernel<<<NBLK, 256>>>((const unsigned int*)ei, flux);
    cudaEventRecord(evDet, 0);
    cudaStreamWaitEvent(s2, evDet, 0);
    fill_kernel<<<(N_EDGES / 2 + 255) / 256, 256, 0, s2>>>(ei, fdo);
    cudaEventRecord(evFill, s2);

    hist_kernel<<<(N_EDGES / 4 + 255) / 256, 256>>>(ei);
    dis_kernel<<<NBLK, 256>>>();

    // gather batch 0 after chain+fill+gemm0; batch 1 after gemm1
    cudaStreamWaitEvent(0, evFill, 0);
    cudaStreamWaitEvent(0, evG0, 0);
    gather_kernel<<<(N_NODES * 32 + 127) / 128, 128>>>(0, bias, out);
    cudaStreamWaitEvent(0, evG1, 0);
    gather_kernel<<<(N_NODES * 32 + 127) / 128, 128>>>(1, bias, out);
}